// round 16
// baseline (speedup 1.0000x reference)
#include <cuda_runtime.h>
#include <cstdint>

// AccRNNCell R16: collapsed recurrence + 2-CTA N-split cluster + 4col x 8row
// register tile (32 MACs/k/thread, 16 FFMA2). NG=8 k-groups x 64 threads.
//   ns0 = h0@WA0 + [xt,acc]@WB0 + f0
//   ns1 = h1@WA1 + ns0@E1 + f1
//   ns2 = h2@WA2 + ns1@E2 + f2
//   res = ns2@Eout + fout ; acc += res
// Per CTA: N-cols [rank*256,(rank+1)*256), 8 batch rows, DSMEM broadcast of
// each stage's half-state to the peer; hsT parity double-buffered.

#define UU 512
#define FF 64
#define PP 32
#define BT 8          // batch rows per cluster
#define NH 256        // N-cols per CTA
#define TPB 512
#define NG 8
#define TT 512
#define BB 512

typedef unsigned long long u64;

__device__ float dE1[UU * UU];
__device__ float dE2[UU * UU];
__device__ float dEout[UU * PP];
__device__ float df0[UU];
__device__ float df1[UU];
__device__ float df2[UU];
__device__ float dfout[PP];

// hsT[2][3][UU][BT] + inT[96][BT] + part[NG][NH][BT] + accS + wpart
#define SMEM_FLOATS (2*3*UU*BT + 96*BT + NG*NH*BT + BT*PP + TPB)
#define SMEM_BYTES  (SMEM_FLOATS * 4)

// ---------------- precompute (unchanged) ----------------
__global__ void __launch_bounds__(512) precompute(
    const float* __restrict__ WBr, const float* __restrict__ bBr,
    const float* __restrict__ WC,  const float* __restrict__ bC,
    const float* __restrict__ Wout, const float* __restrict__ bout,
    const float* __restrict__ bA,  const float* __restrict__ bB0)
{
    const int bid = blockIdx.x, tid = threadIdx.x;
    __shared__ float row[UU];
    if (bid < 2 * UU) {
        int w = bid >> 9;
        int r = bid & (UU - 1);
        const float* Wc = WC + (size_t)w * UU * UU + (size_t)r * UU;
        const float* Wb = WBr + (size_t)w * UU * UU;
        float* E = w ? dE2 : dE1;
        row[tid] = Wc[tid];
        __syncthreads();
        float s = 0.f;
        #pragma unroll 8
        for (int m = 0; m < UU; ++m)
            s = fmaf(row[m], Wb[(size_t)m * UU + tid], s);
        E[(size_t)r * UU + tid] = s;
    } else if (bid < 3 * UU) {
        int r = bid - 2 * UU;
        const float* Wc = WC + (size_t)2 * UU * UU + (size_t)r * UU;
        int kg = tid >> 5, p = tid & 31;
        float s = 0.f;
        #pragma unroll 8
        for (int m = kg * 32; m < kg * 32 + 32; ++m)
            s = fmaf(Wc[m], Wout[m * PP + p], s);
        row[tid] = s;
        __syncthreads();
        if (tid < PP) {
            float t = 0.f;
            #pragma unroll
            for (int g = 0; g < 16; ++g) t += row[g * 32 + tid];
            dEout[r * PP + tid] = t;
        }
    } else if (bid == 3 * UU) {
        df0[tid] = bA[tid] + bB0[tid];
    } else if (bid == 3 * UU + 1) {
        float s = bA[UU + tid] + bBr[tid];
        #pragma unroll 8
        for (int m = 0; m < UU; ++m)
            s = fmaf(bC[m], WBr[(size_t)m * UU + tid], s);
        df1[tid] = s;
    } else if (bid == 3 * UU + 2) {
        float s = bA[2 * UU + tid] + bBr[UU + tid];
        #pragma unroll 8
        for (int m = 0; m < UU; ++m)
            s = fmaf(bC[UU + m], WBr[(size_t)UU * UU + (size_t)m * UU + tid], s);
        df2[tid] = s;
    } else {
        if (tid < PP) {
            float s = bout[tid];
            #pragma unroll 8
            for (int m = 0; m < UU; ++m)
                s = fmaf(bC[2 * UU + m], Wout[m * PP + tid], s);
            dfout[tid] = s;
        }
    }
}

// ---------------- device helpers ----------------
__device__ __forceinline__ u64 pack2(float x, float y) {
    u64 v; asm("mov.b64 %0, {%1, %2};" : "=l"(v) : "f"(x), "f"(y)); return v;
}
__device__ __forceinline__ uint32_t smem_u32(const void* p) {
    uint32_t a;
    asm("{ .reg .u64 t; cvta.to.shared.u64 t, %1; cvt.u32.u64 %0, t; }"
        : "=r"(a) : "l"(p));
    return a;
}
__device__ __forceinline__ void st_peer_f4(uint32_t laddr, uint32_t peer, float4 v) {
    uint32_t r;
    asm("mapa.shared::cluster.u32 %0, %1, %2;" : "=r"(r) : "r"(laddr), "r"(peer));
    asm volatile("st.shared::cluster.v4.b32 [%0], {%1,%2,%3,%4};"
                 :: "r"(r), "r"(__float_as_uint(v.x)), "r"(__float_as_uint(v.y)),
                    "r"(__float_as_uint(v.z)), "r"(__float_as_uint(v.w)) : "memory");
}
#define CLUSTER_BAR() do { \
    asm volatile("barrier.cluster.arrive.aligned;" ::: "memory"); \
    asm volatile("barrier.cluster.wait.aligned;"   ::: "memory"); } while (0)

// 4 cols x 8 rows per thread. a[c*4+h] = f32x2 rows (2h,2h+1) of col j0+c.
__device__ __forceinline__ void fma4(const float4* __restrict__ w,
                                     const float* __restrict__ S,
                                     u64* __restrict__ a)
{
    #pragma unroll
    for (int i = 0; i < 4; ++i) {
        ulonglong2 h01 = *reinterpret_cast<const ulonglong2*>(S + i * BT);
        ulonglong2 h23 = *reinterpret_cast<const ulonglong2*>(S + i * BT + 4);
        u64 w0 = pack2(w[i].x, w[i].x), w1 = pack2(w[i].y, w[i].y);
        u64 w2 = pack2(w[i].z, w[i].z), w3 = pack2(w[i].w, w[i].w);
        asm("fma.rn.f32x2 %0, %1, %2, %0;" : "+l"(a[0])  : "l"(w0), "l"(h01.x));
        asm("fma.rn.f32x2 %0, %1, %2, %0;" : "+l"(a[1])  : "l"(w0), "l"(h01.y));
        asm("fma.rn.f32x2 %0, %1, %2, %0;" : "+l"(a[2])  : "l"(w0), "l"(h23.x));
        asm("fma.rn.f32x2 %0, %1, %2, %0;" : "+l"(a[3])  : "l"(w0), "l"(h23.y));
        asm("fma.rn.f32x2 %0, %1, %2, %0;" : "+l"(a[4])  : "l"(w1), "l"(h01.x));
        asm("fma.rn.f32x2 %0, %1, %2, %0;" : "+l"(a[5])  : "l"(w1), "l"(h01.y));
        asm("fma.rn.f32x2 %0, %1, %2, %0;" : "+l"(a[6])  : "l"(w1), "l"(h23.x));
        asm("fma.rn.f32x2 %0, %1, %2, %0;" : "+l"(a[7])  : "l"(w1), "l"(h23.y));
        asm("fma.rn.f32x2 %0, %1, %2, %0;" : "+l"(a[8])  : "l"(w2), "l"(h01.x));
        asm("fma.rn.f32x2 %0, %1, %2, %0;" : "+l"(a[9])  : "l"(w2), "l"(h01.y));
        asm("fma.rn.f32x2 %0, %1, %2, %0;" : "+l"(a[10]) : "l"(w2), "l"(h23.x));
        asm("fma.rn.f32x2 %0, %1, %2, %0;" : "+l"(a[11]) : "l"(w2), "l"(h23.y));
        asm("fma.rn.f32x2 %0, %1, %2, %0;" : "+l"(a[12]) : "l"(w3), "l"(h01.x));
        asm("fma.rn.f32x2 %0, %1, %2, %0;" : "+l"(a[13]) : "l"(w3), "l"(h01.y));
        asm("fma.rn.f32x2 %0, %1, %2, %0;" : "+l"(a[14]) : "l"(w3), "l"(h23.x));
        asm("fma.rn.f32x2 %0, %1, %2, %0;" : "+l"(a[15]) : "l"(w3), "l"(h23.y));
    }
}
__device__ __forceinline__ void load4w(float4* __restrict__ w, const float* __restrict__ W)
{
    #pragma unroll
    for (int i = 0; i < 4; ++i)
        w[i] = __ldg(reinterpret_cast<const float4*>(W + (size_t)i * UU));
}

template<int K>
__device__ __forceinline__ void gemm4(const float* __restrict__ W,   // +kbeg*UU + jcol
                                      const float* __restrict__ S,   // +kbeg*BT
                                      u64* __restrict__ a)
{
    static_assert(K % 16 == 0 && K >= 16, "K must be multiple of 16");
    float4 wa[4], wb[4];
    load4w(wa, W);
    #pragma unroll 2
    for (int k0 = 0; k0 < K - 8; k0 += 8) {
        load4w(wb, W + (size_t)(k0 + 4) * UU);
        fma4(wa, S + k0 * BT, a);
        load4w(wa, W + (size_t)(k0 + 8) * UU);
        fma4(wb, S + (k0 + 4) * BT, a);
    }
    load4w(wb, W + (size_t)(K - 4) * UU);
    fma4(wa, S + (K - 8) * BT, a);
    fma4(wb, S + (K - 4) * BT, a);
}

__global__ void __launch_bounds__(TPB, 1) __cluster_dims__(2, 1, 1)
accrnn_persistent(const float* __restrict__ x,
                  const float* __restrict__ WA,
                  const float* __restrict__ WB0,
                  float* __restrict__ out)
{
    extern __shared__ float smem[];
    float* hsT   = smem;                       // [2][3][UU][BT]
    float* inT   = hsT + 2 * 3 * UU * BT;      // [96][BT]
    float* part  = inT + 96 * BT;              // [NG][NH][BT]
    float* accS  = part + NG * NH * BT;        // [BT*PP]
    float* wpart = accS + BT * PP;             // [TPB]

    const int tid = threadIdx.x;
    uint32_t rank; asm("mov.u32 %0, %%cluster_ctarank;" : "=r"(rank));
    const uint32_t peer = rank ^ 1u;
    const int b0  = (blockIdx.x >> 1) * BT;
    const int grp = tid >> 6;          // 0..7
    const int ct  = tid & 63;
    const int jl  = ct * 4;            // local col (0..255), 4 owned
    const int j0  = (int)rank * NH + jl;

    for (int i = tid; i < 2 * 3 * UU * BT; i += TPB) hsT[i] = 0.f;
    if (tid < BT * PP) accS[tid] = 0.f;
    __syncthreads();
    CLUSTER_BAR();

    const int xr = tid >> 6;           // 0..7
    const int xf = tid & 63;
    const float* xrow = x + ((size_t)(b0 + xr) * TT) * FF + xf;

    const int ccol = tid >> 1;         // combine: col 0..255
    const int chalf = (tid & 1) * 4;   // rows 0-3 / 4-7

    for (int t = 0; t < TT; ++t) {
        const int buf = t & 1;
        float* hsNew = hsT + buf * 3 * UU * BT;
        float* hsOld = hsT + (buf ^ 1) * 3 * UU * BT;

        // ---- inT = concat(x_t, acc) ----
        inT[xf * BT + xr] = xrow[(size_t)t * FF];
        if (tid < BT * PP) {
            int r = tid >> 5, p = tid & 31;
            inT[(FF + p) * BT + r] = accS[tid];
        }
        __syncthreads();

        // ======== 3 stages ========
        #pragma unroll
        for (int s = 0; s < 3; ++s) {
            u64 a[16];
            const float* f = (s == 0) ? df0 : (s == 1) ? df1 : df2;
            if (grp == 0) {
                #pragma unroll
                for (int c = 0; c < 4; ++c) {
                    float b = f[j0 + c];
                    u64 bb = pack2(b, b);
                    a[c * 4] = a[c * 4 + 1] = a[c * 4 + 2] = a[c * 4 + 3] = bb;
                }
            } else {
                #pragma unroll
                for (int i = 0; i < 16; ++i) a[i] = 0ull;
            }
            if (s == 0) {
                if (grp < 6) {
                    int kbeg = grp * 80;
                    gemm4<80>(WA + (size_t)kbeg * UU + j0, hsOld + kbeg * BT, a);
                } else if (grp == 6) {
                    gemm4<32>(WA + (size_t)480 * UU + j0, hsOld + 480 * BT, a);
                    gemm4<48>(WB0 + j0, inT, a);
                } else {
                    gemm4<48>(WB0 + (size_t)48 * UU + j0, inT + 48 * BT, a);
                }
            } else {
                if (grp < 4) {
                    int kbeg = grp * 128;
                    gemm4<128>(WA + (size_t)s * UU * UU + (size_t)kbeg * UU + j0,
                               hsOld + s * UU * BT + kbeg * BT, a);
                } else {
                    const float* E = (s == 1) ? dE1 : dE2;
                    int kbeg = (grp - 4) * 128;
                    gemm4<128>(E + (size_t)kbeg * UU + j0,
                               hsNew + (s - 1) * UU * BT + kbeg * BT, a);
                }
            }
            {   // part[grp][jl..jl+3][0..7]
                float* pp = part + grp * NH * BT + jl * BT;
                #pragma unroll
                for (int c = 0; c < 4; ++c) {
                    ulonglong2 v;
                    v.x = a[c * 4];     v.y = a[c * 4 + 1];
                    *reinterpret_cast<ulonglong2*>(pp + c * BT) = v;
                    v.x = a[c * 4 + 2]; v.y = a[c * 4 + 3];
                    *reinterpret_cast<ulonglong2*>(pp + c * BT + 4) = v;
                }
            }
            __syncthreads();
            {   // combine (8-way) + broadcast to peer
                const float* base = part + ccol * BT + chalf;
                float4 sv = *reinterpret_cast<const float4*>(base);
                #pragma unroll
                for (int g = 1; g < NG; ++g) {
                    float4 q = *reinterpret_cast<const float4*>(base + g * NH * BT);
                    sv.x += q.x; sv.y += q.y; sv.z += q.z; sv.w += q.w;
                }
                float* dst = hsNew + s * UU * BT + ((int)rank * NH + ccol) * BT + chalf;
                *reinterpret_cast<float4*>(dst) = sv;
                st_peer_f4(smem_u32(dst), peer, sv);
            }
            CLUSTER_BAR();   // peer half visible before next stage reads
        }

        // ======== out: res = ns2 @ Eout + fout ; acc += res ========
        {
            int ks = tid >> 8;                 // 0/1 k-split
            int rp = tid & 255;
            int r = rp >> 5, p = rp & 31;
            const float* n2 = hsNew + 2 * UU * BT;
            float sv = 0.f;
            int kbeg = ks * 256;
            #pragma unroll 8
            for (int k = kbeg; k < kbeg + 256; ++k)
                sv = fmaf(n2[k * BT + r], dEout[k * PP + p], sv);
            wpart[tid] = sv;
        }
        __syncthreads();
        if (tid < BT * PP) {
            int r = tid >> 5, p = tid & 31;
            float tot = wpart[tid] + wpart[tid + 256] + dfout[p];
            accS[tid] += tot;
            if ((uint32_t)(r >> 2) == rank)
                out[((size_t)(b0 + r) * TT + t) * PP + p] = tot;
        }
        __syncthreads();
    }
}

extern "C" void kernel_launch(void* const* d_in, const int* in_sizes, int n_in,
                              void* d_out, int out_size)
{
    const float* x    = (const float*)d_in[0];
    const float* WA   = (const float*)d_in[1];
    const float* bA   = (const float*)d_in[2];
    const float* WB0  = (const float*)d_in[3];
    const float* bB0  = (const float*)d_in[4];
    const float* WBr  = (const float*)d_in[5];
    const float* bBr  = (const float*)d_in[6];
    const float* WC   = (const float*)d_in[7];
    const float* bC   = (const float*)d_in[8];
    const float* Wout = (const float*)d_in[9];
    const float* bout = (const float*)d_in[10];
    float* out = (float*)d_out;

    precompute<<<3 * UU + 4, 512>>>(WBr, bBr, WC, bC, Wout, bout, bA, bB0);

    cudaFuncSetAttribute(accrnn_persistent,
                         cudaFuncAttributeMaxDynamicSharedMemorySize, SMEM_BYTES);
    accrnn_persistent<<<BB / BT * 2, TPB, SMEM_BYTES>>>(x, WA, WB0, out);
}